// round 9
// baseline (speedup 1.0000x reference)
#include <cuda_runtime.h>
#include <math.h>

// Problem constants
#define BB 1024
#define TT 512
#define II 64
#define HH 32
#define BBH (BB * HH)
#define OUT_OFFSET (BB * TT)      // h_last written after outs

// Scratch: x_proj (+ both biases folded) in [T, B, H] layout
__device__ float g_xp[TT * BB * HH];

// Packed fp32x2 FMA / ADD (Blackwell)
__device__ __forceinline__ float2 ffma2(float2 a, float2 b, float2 c) {
    union U { float2 f; unsigned long long u; };
    U ua, ub, uc, ud;
    ua.f = a; ub.f = b; uc.f = c;
    asm("fma.rn.f32x2 %0, %1, %2, %3;"
        : "=l"(ud.u) : "l"(ua.u), "l"(ub.u), "l"(uc.u));
    return ud.f;
}
__device__ __forceinline__ float2 fadd2(float2 a, float2 b) {
    union U { float2 f; unsigned long long u; };
    U ua, ub, uc;
    ua.f = a; ub.f = b;
    asm("add.rn.f32x2 %0, %1, %2;" : "=l"(uc.u) : "l"(ua.u), "l"(ub.u));
    return uc.f;
}

// HW tanh (MUFU.TANH, Turing+): 1 instruction, ~16 cyc, |err| ~1e-5.
__device__ __forceinline__ float fast_tanh(float x) {
    float r;
    asm("tanh.approx.f32 %0, %1;" : "=f"(r) : "f"(x));
    return r;
}

// ---------------------------------------------------------------------------
// Kernel 1: x_proj[t][b][j] = b_ih[j] + b_hh[j] + sum_k x[b][t][k] * W_ih[j][k]
// 8192 warps; each warp owns (b, 64-row t-chunk): contiguous 16KB LDG stream.
// 8-row chunks double-buffered in smem; ONE syncwarp per 8 rows; LDG MLP=8.
// Lane j owns output column j with W_ih row j in registers.
// ---------------------------------------------------------------------------
__global__ __launch_bounds__(256, 2) void xproj_kernel(
    const float* __restrict__ x,
    const float* __restrict__ W_ih,
    const float* __restrict__ b_ih,
    const float* __restrict__ b_hh)
{
    __shared__ __align__(16) float2 sx[8][2][8][32];  // 8 warps x 2 bufs x 8 rows

    const int lane = threadIdx.x & 31;
    const int wid  = threadIdx.x >> 5;
    const int gw   = blockIdx.x * 8 + wid;            // 0..8191
    const int b    = gw >> 3;
    const int t0   = (gw & 7) * 64;

    // Lane j holds W_ih row j as 32 packed pairs
    float2 wx[32];
    {
        const float2* wr = reinterpret_cast<const float2*>(W_ih + lane * II);
#pragma unroll
        for (int m = 0; m < 32; ++m) wx[m] = wr[m];
    }
    const float bias = b_ih[lane] + b_hh[lane];

    const float2* xr = reinterpret_cast<const float2*>(x + ((size_t)b * TT + t0) * II);
    float* gout = g_xp + (size_t)t0 * BBH + b * HH + lane;

    // Prologue: chunk0 -> smem buf0; chunk1 in regs
    float2 ld[8];
#pragma unroll
    for (int i = 0; i < 8; ++i) ld[i] = xr[i * 32 + lane];
#pragma unroll
    for (int i = 0; i < 8; ++i) sx[wid][0][i][lane] = ld[i];
#pragma unroll
    for (int i = 0; i < 8; ++i) ld[i] = xr[(8 + i) * 32 + lane];
    __syncwarp();

    for (int c = 0; c < 8; ++c) {
        const int buf = c & 1;
        // Stage chunk c+1 (already in regs) into buf^1; prefetch chunk c+2.
        // WAR-safe: buf^1 was last read in iter c-1, behind its syncwarp.
        if (c < 7) {
#pragma unroll
            for (int i = 0; i < 8; ++i) sx[wid][buf ^ 1][i][lane] = ld[i];
        }
        if (c < 6) {
#pragma unroll
            for (int i = 0; i < 8; ++i) ld[i] = xr[((c + 2) * 8 + i) * 32 + lane];
        }

        // Compute 8 rows from buf (staged last iter, behind syncwarp)
#pragma unroll
        for (int r = 0; r < 8; ++r) {
            const float4* sp = reinterpret_cast<const float4*>(&sx[wid][buf][r][0]);
            float2 c0 = {bias, 0.f}, c1 = {0.f, 0.f}, c2 = {0.f, 0.f}, c3 = {0.f, 0.f};
#pragma unroll
            for (int m = 0; m < 16; m += 2) {
                float4 v0 = sp[m];
                float4 v1 = sp[m + 1];
                c0 = ffma2(make_float2(v0.x, v0.y), wx[2 * m + 0], c0);
                c1 = ffma2(make_float2(v0.z, v0.w), wx[2 * m + 1], c1);
                c2 = ffma2(make_float2(v1.x, v1.y), wx[2 * m + 2], c2);
                c3 = ffma2(make_float2(v1.z, v1.w), wx[2 * m + 3], c3);
            }
            c0 = fadd2(c0, c1); c2 = fadd2(c2, c3); c0 = fadd2(c0, c2);
            gout[(size_t)(c * 8 + r) * BBH] = c0.x + c0.y;   // 128B coalesced
        }
        __syncwarp();   // orders this iter's STS before next iter's LDS
    }
}

// ---------------------------------------------------------------------------
// Kernel 2: sequential recurrence. One warp per batch element; lane j owns h[j].
// xp streamed via 8-deep register ring (one LDG/step, 8 in flight).
// h broadcast via smem double buffer, ONE syncwarp per step; HW tanh.
// Output dot staged in 33-padded smem transpose, flushed every 16 steps.
// Grid: 128 blocks x 256 threads = 2 warps/SMSP on 128 SMs, uniform.
// ---------------------------------------------------------------------------
__global__ __launch_bounds__(256, 1) void rnn_kernel(
    const float* __restrict__ h0,
    const float* __restrict__ W_hh,
    const float* __restrict__ W_out,
    const float* __restrict__ b_out,
    float* __restrict__ out)
{
    __shared__ __align__(16) float hs[8][2][32];   // double-buffered h per warp
    __shared__ float cmat[8][16][33];              // output-dot transpose, padded

    const int lane = threadIdx.x & 31;
    const int wid  = threadIdx.x >> 5;
    const int b    = blockIdx.x * 8 + wid;         // 128 blocks * 8 warps = 1024

    // Lane j holds W_hh row j as 16 packed pairs
    float2 whh[16];
    {
        const float2* wr = reinterpret_cast<const float2*>(W_hh + lane * HH);
#pragma unroll
        for (int m = 0; m < 16; ++m) whh[m] = wr[m];
    }
    const float wout = W_out[lane];
    const float bout = b_out[0];

    float h = h0[b * HH + lane];
    hs[wid][0][lane] = h;
    __syncwarp();

    const float* xpb  = g_xp + b * HH + lane;
    float* outb = out + (size_t)b * TT;

    // 8-deep xp register ring: xv[t&7] holds xp[t..t+7]
    float xv[8];
#pragma unroll
    for (int i = 0; i < 8; ++i) xv[i] = xpb[(size_t)i * BBH];

#pragma unroll 8
    for (int t = 0; t < TT; ++t) {
        const float xp = xv[t & 7];
        {   // refill slot with xp[t+8] (clamped; surplus values unused)
            int tt = t + 8; if (tt > TT - 1) tt = TT - 1;
            xv[t & 7] = xpb[(size_t)tt * BBH];
        }

        // s = xp + W_hh . h
        const float4* hp = reinterpret_cast<const float4*>(hs[wid][t & 1]);
        float2 a0 = {xp, 0.f}, a1 = {0.f, 0.f}, a2 = {0.f, 0.f}, a3 = {0.f, 0.f};
#pragma unroll
        for (int m = 0; m < 8; m += 2) {
            float4 v0 = hp[m];
            float4 v1 = hp[m + 1];
            a0 = ffma2(make_float2(v0.x, v0.y), whh[2 * m + 0], a0);
            a1 = ffma2(make_float2(v0.z, v0.w), whh[2 * m + 1], a1);
            a2 = ffma2(make_float2(v1.x, v1.y), whh[2 * m + 2], a2);
            a3 = ffma2(make_float2(v1.z, v1.w), whh[2 * m + 3], a3);
        }
        a0 = fadd2(a0, a1); a2 = fadd2(a2, a3); a0 = fadd2(a0, a2);
        h = fast_tanh(a0.x + a0.y);

        hs[wid][(t + 1) & 1][lane] = h;        // feed next step
        cmat[wid][t & 15][lane]    = h * wout; // output-dot contribution
        __syncwarp();

        if ((t & 15) == 15) {
            // 16 outputs; 2 lanes per output (halves), stride-33 rows => conflict-free
            const int tt = lane & 15, hf = lane >> 4;
            const float* row = &cmat[wid][tt][hf * 16];
            float s0 = 0.f, s1 = 0.f, s2 = 0.f, s3 = 0.f;
#pragma unroll
            for (int k = 0; k < 16; k += 4) {
                s0 += row[k + 0]; s1 += row[k + 1];
                s2 += row[k + 2]; s3 += row[k + 3];
            }
            float v = (s0 + s1) + (s2 + s3);
            v += __shfl_down_sync(0xffffffffu, v, 16);
            if (lane < 16) outb[t - 15 + lane] = v + bout;  // 64B coalesced
            __syncwarp();   // protect cmat reuse next step
        }
    }

    // h_last [1, B, H] appended after outs
    out[OUT_OFFSET + b * HH + lane] = h;
}

extern "C" void kernel_launch(void* const* d_in, const int* in_sizes, int n_in,
                              void* d_out, int out_size) {
    const float* x     = (const float*)d_in[0];
    const float* h0    = (const float*)d_in[1];
    const float* W_ih  = (const float*)d_in[2];
    const float* b_ih  = (const float*)d_in[3];
    const float* W_hh  = (const float*)d_in[4];
    const float* b_hh  = (const float*)d_in[5];
    const float* W_out = (const float*)d_in[6];
    const float* b_out = (const float*)d_in[7];
    float* out = (float*)d_out;

    (void)in_sizes; (void)n_in; (void)out_size;

    xproj_kernel<<<1024, 256>>>(x, W_ih, b_ih, b_hh);
    rnn_kernel<<<128, 256>>>(h0, W_hh, W_out, b_out, out);
}

// round 10
// speedup vs baseline: 1.5422x; 1.5422x over previous
#include <cuda_runtime.h>
#include <math.h>

// Problem constants
#define BB 1024
#define TT 512
#define II 64
#define HH 32
#define OUT_OFFSET (BB * TT)      // h_last written after outs

// HW tanh (MUFU.TANH): 1 instruction, ~16 cyc, |err| ~1e-5 (validated 4.8e-6 e2e).
__device__ __forceinline__ float fast_tanh(float x) {
    float r;
    asm("tanh.approx.f32 %0, %1;" : "=f"(r) : "f"(x));
    return r;
}

// ---------------------------------------------------------------------------
// Fused RNN, scalar-FFMA version: one warp per batch element, all T=512 steps.
//  - lane j owns h[j]; W_ih row j (64 floats) and W_hh row j (32 floats) in regs
//  - x[b] rows streamed via 8-deep per-warp smem ring (verified schedule):
//      step t: stage row t+8 into slot t&7 (row t dead since step t-1's sync),
//              prefetch row t+12 into pre[t&3]; read row t+1 from slot (t+1)&7.
//  - x_proj for step t+1 computed inside step t (off the h dependency chain)
//  - all smem reads are warp-broadcast float4 (1 wavefront each)
//  - NO f32x2: plain FFMA, no register-pair marshaling MOVs
//  - h broadcast via smem double buffer, ONE __syncwarp per step
//  - output dot staged in 33-padded smem transpose, flushed every 16 steps
// Grid: 128 blocks x 256 threads = 1024 warps = 2 warps/SMSP on 128 SMs.
// ---------------------------------------------------------------------------
__global__ __launch_bounds__(256, 1) void rnn_fused_kernel(
    const float* __restrict__ x,
    const float* __restrict__ h0,
    const float* __restrict__ W_ih,
    const float* __restrict__ b_ih,
    const float* __restrict__ W_hh,
    const float* __restrict__ b_hh,
    const float* __restrict__ W_out,
    const float* __restrict__ b_out,
    float* __restrict__ out)
{
    __shared__ __align__(16) float2 sx[8][8][32];   // 8 warps, 8-row x ring
    __shared__ __align__(16) float  hs[8][2][32];   // double-buffered h
    __shared__ float cmat[8][16][33];               // output-dot transpose, padded

    const int lane = threadIdx.x & 31;
    const int wid  = threadIdx.x >> 5;
    const int b    = blockIdx.x * 8 + wid;          // 128 blocks * 8 warps = 1024

    // Weights in registers (scalar): lane j holds row j
    float wxs[64];
    {
        const float4* wr = reinterpret_cast<const float4*>(W_ih + lane * II);
#pragma unroll
        for (int m = 0; m < 16; ++m) {
            float4 v = wr[m];
            wxs[4 * m + 0] = v.x; wxs[4 * m + 1] = v.y;
            wxs[4 * m + 2] = v.z; wxs[4 * m + 3] = v.w;
        }
    }
    float whs[32];
    {
        const float4* wr = reinterpret_cast<const float4*>(W_hh + lane * HH);
#pragma unroll
        for (int m = 0; m < 8; ++m) {
            float4 v = wr[m];
            whs[4 * m + 0] = v.x; whs[4 * m + 1] = v.y;
            whs[4 * m + 2] = v.z; whs[4 * m + 3] = v.w;
        }
    }
    const float bias = b_ih[lane] + b_hh[lane];     // folded into x_proj
    const float wout = W_out[lane];
    const float bout = b_out[0];

    const float2* xr = reinterpret_cast<const float2*>(x + (size_t)b * TT * II);
    float* outb = out + (size_t)b * TT;

    // Prologue: stage x rows 0..7 into slots 0..7; pre[i] holds row 8+i
    // (invariant: at step t, pre[t&3] holds row t+8).
#pragma unroll
    for (int i = 0; i < 8; ++i) sx[wid][i][lane] = xr[i * 32 + lane];
    float2 pre[4];
#pragma unroll
    for (int i = 0; i < 4; ++i) pre[i] = xr[(8 + i) * 32 + lane];

    float h = h0[b * HH + lane];
    hs[wid][0][lane] = h;
    __syncwarp();

    // x_proj for step 0 (row 0, slot 0), scalar FFMA, 4 chains depth 16
    float xp_cur;
    {
        const float4* sp = reinterpret_cast<const float4*>(sx[wid][0]);
        float c0 = bias, c1 = 0.f, c2 = 0.f, c3 = 0.f;
#pragma unroll
        for (int m = 0; m < 16; ++m) {
            float4 v = sp[m];
            c0 = fmaf(v.x, wxs[4 * m + 0], c0);
            c1 = fmaf(v.y, wxs[4 * m + 1], c1);
            c2 = fmaf(v.z, wxs[4 * m + 2], c2);
            c3 = fmaf(v.w, wxs[4 * m + 3], c3);
        }
        xp_cur = (c0 + c1) + (c2 + c3);
    }

#pragma unroll 4
    for (int t = 0; t < TT; ++t) {
        // Stage row t+8 into slot t&7 (dead since step t-1's syncwarp);
        // prefetch row t+12 (clamped) into the pre ring.
        sx[wid][t & 7][lane] = pre[t & 3];
        pre[t & 3] = xr[min(t + 12, TT - 1) * 32 + lane];

        // --- x_proj for step t+1 (row t+1, slot (t+1)&7: staged at step t-7) ---
        const float4* sp = reinterpret_cast<const float4*>(sx[wid][(t + 1) & 7]);
        float c0 = bias, c1 = 0.f, c2 = 0.f, c3 = 0.f;
#pragma unroll
        for (int m = 0; m < 16; ++m) {
            float4 v = sp[m];
            c0 = fmaf(v.x, wxs[4 * m + 0], c0);
            c1 = fmaf(v.y, wxs[4 * m + 1], c1);
            c2 = fmaf(v.z, wxs[4 * m + 2], c2);
            c3 = fmaf(v.w, wxs[4 * m + 3], c3);
        }
        const float xp_next = (c0 + c1) + (c2 + c3);

        // --- recurrence: s = xp_cur + W_hh . h  (4 chains depth 8) ---
        const float4* hp = reinterpret_cast<const float4*>(hs[wid][t & 1]);
        float a0 = xp_cur, a1 = 0.f, a2 = 0.f, a3 = 0.f;
#pragma unroll
        for (int m = 0; m < 8; ++m) {
            float4 v = hp[m];
            a0 = fmaf(v.x, whs[4 * m + 0], a0);
            a1 = fmaf(v.y, whs[4 * m + 1], a1);
            a2 = fmaf(v.z, whs[4 * m + 2], a2);
            a3 = fmaf(v.w, whs[4 * m + 3], a3);
        }
        h = fast_tanh((a0 + a1) + (a2 + a3));

        hs[wid][(t + 1) & 1][lane] = h;        // feed next step
        cmat[wid][t & 15][lane]    = h * wout; // output-dot contribution
        __syncwarp();

        if ((t & 15) == 15) {
            // 16 outputs; 2 lanes per output (halves), stride-33 rows => conflict-free
            const int tt = lane & 15, hf = lane >> 4;
            const float* row = &cmat[wid][tt][hf * 16];
            float s0 = 0.f, s1 = 0.f, s2 = 0.f, s3 = 0.f;
#pragma unroll
            for (int k = 0; k < 16; k += 4) {
                s0 += row[k + 0]; s1 += row[k + 1];
                s2 += row[k + 2]; s3 += row[k + 3];
            }
            float v = (s0 + s1) + (s2 + s3);
            v += __shfl_down_sync(0xffffffffu, v, 16);
            if (lane < 16) outb[t - 15 + lane] = v + bout;  // 64B coalesced
            __syncwarp();   // protect cmat reuse next step
        }

        xp_cur = xp_next;
    }

    // h_last [1, B, H] appended after outs
    out[OUT_OFFSET + b * HH + lane] = h;
}

extern "C" void kernel_launch(void* const* d_in, const int* in_sizes, int n_in,
                              void* d_out, int out_size) {
    const float* x     = (const float*)d_in[0];
    const float* h0    = (const float*)d_in[1];
    const float* W_ih  = (const float*)d_in[2];
    const float* b_ih  = (const float*)d_in[3];
    const float* W_hh  = (const float*)d_in[4];
    const float* b_hh  = (const float*)d_in[5];
    const float* W_out = (const float*)d_in[6];
    const float* b_out = (const float*)d_in[7];
    float* out = (float*)d_out;

    (void)in_sizes; (void)n_in; (void)out_size;

    rnn_fused_kernel<<<128, 256>>>(x, h0, W_ih, b_ih, W_hh, b_hh, W_out, b_out, out);
}

// round 15
// speedup vs baseline: 1.6909x; 1.0964x over previous
#include <cuda_runtime.h>
#include <cstdint>
#include <math.h>

// Problem constants
#define BB 1024
#define TT 512
#define II 64
#define HH 32
#define OUT_OFFSET (BB * TT)      // h_last written after outs

#define NWARP 7                    // warps per block
#define NBLK  147                  // 147 * 7 = 1029 >= 1024 warps

typedef unsigned long long u64;
typedef unsigned int u32;

// ---- b64-domain f32x2 helpers: values live in 64-bit regs (aligned pairs),
// ---- no float<->pair marshaling MOVs anywhere in the hot loop.
__device__ __forceinline__ u64 pack2(float lo, float hi) {
    u64 r; asm("mov.b64 %0, {%1, %2};" : "=l"(r) : "f"(lo), "f"(hi)); return r;
}
__device__ __forceinline__ void unpack2(float& lo, float& hi, u64 v) {
    asm("mov.b64 {%0, %1}, %2;" : "=f"(lo), "=f"(hi) : "l"(v));
}
__device__ __forceinline__ u64 ffma2(u64 a, u64 b, u64 c) {
    u64 d; asm("fma.rn.f32x2 %0, %1, %2, %3;" : "=l"(d) : "l"(a), "l"(b), "l"(c));
    return d;
}
__device__ __forceinline__ u64 fadd2(u64 a, u64 b) {
    u64 d; asm("add.rn.f32x2 %0, %1, %2;" : "=l"(d) : "l"(a), "l"(b)); return d;
}

// HW tanh (MUFU.TANH): 1 instruction, |err| ~1e-5 (validated 4.8e-6 e2e).
__device__ __forceinline__ float fast_tanh(float x) {
    float r; asm("tanh.approx.f32 %0, %1;" : "=f"(r) : "f"(x)); return r;
}

// dot of 64 floats (16 x 16B smem, warp-broadcast) with 32 packed weight pairs
__device__ __forceinline__ float dot64(u32 sa, const u64* w2, u64 init) {
    u64 c0 = init, c1 = 0ull, c2 = 0ull, c3 = 0ull;
#pragma unroll
    for (int m = 0; m < 16; m += 2) {
        u64 q0, q1, q2, q3;
        asm volatile("ld.shared.v2.u64 {%0,%1}, [%2];"
                     : "=l"(q0), "=l"(q1) : "r"(sa + m * 16));
        asm volatile("ld.shared.v2.u64 {%0,%1}, [%2];"
                     : "=l"(q2), "=l"(q3) : "r"(sa + m * 16 + 16));
        c0 = ffma2(q0, w2[2 * m + 0], c0);
        c1 = ffma2(q1, w2[2 * m + 1], c1);
        c2 = ffma2(q2, w2[2 * m + 2], c2);
        c3 = ffma2(q3, w2[2 * m + 3], c3);
    }
    u64 c = fadd2(fadd2(c0, c1), fadd2(c2, c3));
    float lo, hi; unpack2(lo, hi, c);
    return lo + hi;
}

// dot of 32 floats (8 x 16B smem, warp-broadcast) with 16 packed weight pairs
__device__ __forceinline__ float dot32(u32 sa, const u64* w2, u64 init) {
    u64 c0 = init, c1 = 0ull, c2 = 0ull, c3 = 0ull;
#pragma unroll
    for (int m = 0; m < 8; m += 2) {
        u64 q0, q1, q2, q3;
        asm volatile("ld.shared.v2.u64 {%0,%1}, [%2];"
                     : "=l"(q0), "=l"(q1) : "r"(sa + m * 16));
        asm volatile("ld.shared.v2.u64 {%0,%1}, [%2];"
                     : "=l"(q2), "=l"(q3) : "r"(sa + m * 16 + 16));
        c0 = ffma2(q0, w2[2 * m + 0], c0);
        c1 = ffma2(q1, w2[2 * m + 1], c1);
        c2 = ffma2(q2, w2[2 * m + 2], c2);
        c3 = ffma2(q3, w2[2 * m + 3], c3);
    }
    u64 c = fadd2(fadd2(c0, c1), fadd2(c2, c3));
    float lo, hi; unpack2(lo, hi, c);
    return lo + hi;
}

// ---------------------------------------------------------------------------
// Fused RNN, b64/f32x2 version: one warp per batch element, all T=512 steps.
//  - lane j owns h[j]; W_ih row j (32 u64 pairs), W_hh row j (16 u64 pairs) regs
//  - x[b] rows streamed via 8-deep per-warp smem ring (verified schedule):
//      step t: stage row t+8 into slot t&7, prefetch row t+12 into pre[t&3];
//      read row t+1 from slot (t+1)&7 (staged 7 syncwarps ago).
//  - x_proj for step t+1 computed inside step t (off the h dependency chain)
//  - h broadcast via smem double buffer, ONE __syncwarp per step
//  - output dot staged in 33-padded smem transpose, flushed every 16 steps
// Grid: 147 blocks x 7 warps -> spreads smem-wavefront load over 147 SMs.
// ---------------------------------------------------------------------------
__global__ __launch_bounds__(NWARP * 32, 1) void rnn_fused_kernel(
    const float* __restrict__ x,
    const float* __restrict__ h0,
    const float* __restrict__ W_ih,
    const float* __restrict__ b_ih,
    const float* __restrict__ W_hh,
    const float* __restrict__ b_hh,
    const float* __restrict__ W_out,
    const float* __restrict__ b_out,
    float* __restrict__ out)
{
    __shared__ __align__(16) u64   sx[NWARP][8][32];   // x ring: 8 rows x 256B
    __shared__ __align__(16) float hs[NWARP][2][32];   // double-buffered h
    __shared__ float cmat[NWARP][16][33];              // output-dot transpose

    const int lane = threadIdx.x & 31;
    const int wid  = threadIdx.x >> 5;
    const int b    = blockIdx.x * NWARP + wid;
    if (b >= BB) return;                               // only __syncwarp below

    // Weights in b64 pairs: lane j holds row j
    u64 wx2[32];
    {
        const u64* wr = reinterpret_cast<const u64*>(W_ih + lane * II);
#pragma unroll
        for (int m = 0; m < 32; ++m) wx2[m] = wr[m];
    }
    u64 wh2[16];
    {
        const u64* wr = reinterpret_cast<const u64*>(W_hh + lane * HH);
#pragma unroll
        for (int m = 0; m < 16; ++m) wh2[m] = wr[m];
    }
    const float bias = b_ih[lane] + b_hh[lane];        // folded into x_proj
    const u64  bias2 = pack2(bias, 0.f);
    const float wout = W_out[lane];
    const float bout = b_out[0];

    const u32 sx_base = (u32)__cvta_generic_to_shared(&sx[wid][0][0]);
    const u32 hs_base = (u32)__cvta_generic_to_shared(&hs[wid][0][0]);

    const u64* xr = reinterpret_cast<const u64*>(x + (size_t)b * TT * II);
    float* outb = out + (size_t)b * TT;

    // Prologue: stage x rows 0..7 into slots 0..7; pre[i] holds row 8+i
    // (invariant: at step t, pre[t&3] holds row t+8).
#pragma unroll
    for (int i = 0; i < 8; ++i) sx[wid][i][lane] = xr[i * 32 + lane];
    u64 pre[4];
#pragma unroll
    for (int i = 0; i < 4; ++i) pre[i] = xr[(8 + i) * 32 + lane];

    float h = h0[b * HH + lane];
    hs[wid][0][lane] = h;
    __syncwarp();

    // x_proj for step 0 (row 0, slot 0)
    float xp_cur = dot64(sx_base, wx2, bias2);

#pragma unroll 4
    for (int t = 0; t < TT; ++t) {
        // Stage row t+8 into slot t&7 (dead since step t-1's syncwarp);
        // prefetch row t+12 (clamped) into the pre ring.
        sx[wid][t & 7][lane] = pre[t & 3];
        pre[t & 3] = xr[min(t + 12, TT - 1) * 32 + lane];

        // --- x_proj for step t+1 (slot (t+1)&7, staged at step t-7) ---
        const float xp_next = dot64(sx_base + ((t + 1) & 7) * 256, wx2, bias2);

        // --- recurrence: s = xp_cur + W_hh . h ---
        const float s = dot32(hs_base + (t & 1) * 128, wh2, pack2(xp_cur, 0.f));
        h = fast_tanh(s);

        hs[wid][(t + 1) & 1][lane] = h;        // feed next step
        cmat[wid][t & 15][lane]    = h * wout; // output-dot contribution
        __syncwarp();

        if ((t & 15) == 15) {
            // 16 outputs; 2 lanes per output (halves), stride-33 => conflict-free
            const int tt = lane & 15, hf = lane >> 4;
            const float* row = &cmat[wid][tt][hf * 16];
            float s0 = 0.f, s1 = 0.f, s2 = 0.f, s3 = 0.f;
#pragma unroll
            for (int k = 0; k < 16; k += 4) {
                s0 += row[k + 0]; s1 += row[k + 1];
                s2 += row[k + 2]; s3 += row[k + 3];
            }
            float v = (s0 + s1) + (s2 + s3);
            v += __shfl_down_sync(0xffffffffu, v, 16);
            if (lane < 16) outb[t - 15 + lane] = v + bout;  // 64B coalesced
            __syncwarp();   // protect cmat reuse next step
        }

        xp_cur = xp_next;
    }

    // h_last [1, B, H] appended after outs
    out[OUT_OFFSET + b * HH + lane] = h;
}

extern "C" void kernel_launch(void* const* d_in, const int* in_sizes, int n_in,
                              void* d_out, int out_size) {
    const float* x     = (const float*)d_in[0];
    const float* h0    = (const float*)d_in[1];
    const float* W_ih  = (const float*)d_in[2];
    const float* b_ih  = (const float*)d_in[3];
    const float* W_hh  = (const float*)d_in[4];
    const float* b_hh  = (const float*)d_in[5];
    const float* W_out = (const float*)d_in[6];
    const float* b_out = (const float*)d_in[7];
    float* out = (float*)d_out;

    (void)in_sizes; (void)n_in; (void)out_size;

    rnn_fused_kernel<<<NBLK, NWARP * 32>>>(x, h0, W_ih, b_ih, W_hh, b_hh,
                                           W_out, b_out, out);
}